// round 17
// baseline (speedup 1.0000x reference)
#include <cuda_runtime.h>
#include <cuda_fp16.h>
#include <math.h>

#define BB   128
#define SS   400
#define EE   512
#define TT   300
#define VV   30
#define EMBD 256
#define H1   512
#define H2   128
#define PP   128
#define G1   2048
#define G2   512
#define NCTA 128
#define NTHR 256
#define PRED_N (BB*VV*TT)

typedef unsigned long long u64;

// ---------------- device scratch ----------------
// Gate-interleaved columns: jn = 4*h + gate (0=i,1=f,2=g,3=o)
__device__ __align__(16) __half  g_keysh [BB*SS*PP];   // fp16 keys [b][s][p]
__device__ __align__(16) __half  g_valsh [BB*SS*PP];   // fp16 values [b][s][p]
__device__ __align__(16) __half  g_W1h   [640*G1];     // [k][jn]: k<128 ctx, else W_hh1
__device__ __align__(16) __half  g_W2h   [640*G2];     // [k][jn]: k<512 W_ih2, else W_hh2
__device__ __align__(16) float   g_MembT [G1*32];      // [jn][tok]
__device__ __align__(16) float   g_b2    [G2];         // [jn]
// xT rows: [0,128) ctx | 128+slot*512 h1 slots | 1152+slot*128 h2 slots
__device__ __align__(16) float   g_xT    [1408*BB];
__device__ unsigned g_flags[NCTA*32];                  // per-CTA padded barrier flags

__device__ __forceinline__ float sigf(float x) { return 1.f / (1.f + expf(-x)); }

__device__ __forceinline__ u64 ffma2(u64 a, u64 b, u64 c) {
    u64 d; asm("fma.rn.f32x2 %0,%1,%2,%3;" : "=l"(d) : "l"(a), "l"(b), "l"(c)); return d;
}
__device__ __forceinline__ u64 pack2(float v) {
    u64 d; asm("mov.b64 %0,{%1,%1};" : "=l"(d) : "f"(v)); return d;
}
__device__ __forceinline__ float2 unpk(u64 d) {
    float2 f; asm("mov.b64 {%0,%1},%2;" : "=f"(f.x), "=f"(f.y) : "l"(d)); return f;
}
__device__ __forceinline__ unsigned ld_acq(unsigned* p) {
    unsigned v; asm volatile("ld.acquire.gpu.u32 %0, [%1];" : "=r"(v) : "l"(p) : "memory"); return v;
}
__device__ __forceinline__ void st_rel(unsigned* p, unsigned v) {
    asm volatile("st.release.gpu.u32 [%0], %1;" :: "l"(p), "r"(v) : "memory");
}

__device__ __forceinline__ void fma16(float4& a0, float4& a1, float4& a2, float4& a3,
                                      float4 xv, float4 wv) {
    a0.x += xv.x*wv.x; a0.y += xv.x*wv.y; a0.z += xv.x*wv.z; a0.w += xv.x*wv.w;
    a1.x += xv.y*wv.x; a1.y += xv.y*wv.y; a1.z += xv.y*wv.z; a1.w += xv.y*wv.w;
    a2.x += xv.z*wv.x; a2.y += xv.z*wv.y; a2.z += xv.z*wv.z; a2.w += xv.z*wv.w;
    a3.x += xv.w*wv.x; a3.y += xv.w*wv.y; a3.z += xv.w*wv.z; a3.w += xv.w*wv.w;
}

// ---- group-local barrier: 64 arrivals, distinct lines, hot acquire spin ----
__device__ __forceinline__ void groupbar(int g, int tid, unsigned& epoch) {
    epoch++;
    __syncthreads();
    if (tid == 0) st_rel(&g_flags[(blockIdx.x) * 32], epoch);
    if (tid < 64) { while (ld_acq(&g_flags[(g * 64 + tid) * 32]) < epoch) { } }
    __syncthreads();
}

// ---------------- precompute: weights pack + Memb (merged) ----------------
__global__ void prep_kernel(const float* __restrict__ Wih1, const float* __restrict__ Whh1,
                            const float* __restrict__ Wih2, const float* __restrict__ Whh2,
                            const float* __restrict__ bih1, const float* __restrict__ bhh1,
                            const float* __restrict__ bih2, const float* __restrict__ bhh2,
                            const float* __restrict__ emb) {
    int gid = blockIdx.x * blockDim.x + threadIdx.x;
    if (gid < 640 * G1) {
        int k = gid / G1, jn = gid % G1;
        int h = jn >> 2, gate = jn & 3, jo = gate * H1 + h;
        float w = (k < PP) ? Wih1[jo * (EMBD + PP) + k] : Whh1[jo * H1 + (k - PP)];
        g_W1h[gid] = __float2half(w);
    } else if (gid < 640 * G1 + 640 * G2) {
        int g2 = gid - 640 * G1;
        int k = g2 / G2, jn = g2 % G2;
        int h = jn >> 2, gate = jn & 3, jo = gate * H2 + h;
        float w = (k < H1) ? Wih2[jo * H1 + k] : Whh2[jo * H2 + (k - H1)];
        g_W2h[g2] = __float2half(w);
    } else if (gid < 640 * G1 + 640 * G2 + G2) {
        int jn = gid - 640 * G1 - 640 * G2;
        int h = jn >> 2, gate = jn & 3, jo = gate * H2 + h;
        g_b2[jn] = bih2[jo] + bhh2[jo];
    } else {
        int idx = gid - (640 * G1 + 640 * G2 + G2);
        if (idx < VV * G1) {
            int v = idx / G1, jn = idx % G1;
            int h = jn >> 2, gate = jn & 3, jo = gate * H1 + h;
            const float* er = emb + v * EMBD;
            const float* wr = Wih1 + jo * (EMBD + PP) + PP;
            float s = bih1[jo] + bhh1[jo];
            for (int k = 0; k < EMBD; k++) s += er[k] * wr[k];
            g_MembT[jn * 32 + v] = s;
        }
    }
}

// keys/values precompute (f32x2 compute, fp16 store)
__global__ __launch_bounds__(256) void kv_kernel(
    const float* __restrict__ enc,
    const float* __restrict__ Wk, const float* __restrict__ bk,
    const float* __restrict__ Wv, const float* __restrict__ bv) {
    __align__(16) __shared__ float sh[10752];
    float* xs = sh;          // [64][132]
    float* ws = sh + 8448;   // [64][36]
    int rt = blockIdx.x;
    int m = blockIdx.y;
    int mat = m >> 2, jt = m & 3;
    const float* W    = mat ? Wv : Wk;
    const float* bias = mat ? bv : bk;
    __half* outh      = mat ? g_valsh : g_keysh;
    int r0 = rt * 128, j0 = jt * 32;
    int tid = threadIdx.x;
    int tb = tid >> 3, tj = tid & 7;
    u64 acc[2][4];
    #pragma unroll
    for (int i = 0; i < 2; i++)
        #pragma unroll
        for (int c = 0; c < 4; c++) acc[i][c] = 0ull;
    for (int kc = 0; kc < EE; kc += 64) {
        #pragma unroll
        for (int i = 0; i < 32; i++) {
            int lin = i * 256 + tid;
            int br = lin >> 6, kk = lin & 63;
            xs[kk * 132 + br] = enc[(size_t)(r0 + br) * EE + kc + kk];
        }
        #pragma unroll
        for (int i = 0; i < 8; i++) {
            int lin = i * 256 + tid;
            int jj = lin >> 6, kk = lin & 63;
            ws[kk * 36 + jj] = W[(j0 + jj) * EE + kc + kk];
        }
        __syncthreads();
        #pragma unroll 16
        for (int kk = 0; kk < 64; kk++) {
            ulonglong2 xv = *(const ulonglong2*)&xs[kk * 132 + tb * 4];
            float4 wv = *(const float4*)&ws[kk * 36 + tj * 4];
            u64 w0 = pack2(wv.x), w1 = pack2(wv.y), w2 = pack2(wv.z), w3 = pack2(wv.w);
            acc[0][0] = ffma2(xv.x, w0, acc[0][0]);
            acc[0][1] = ffma2(xv.x, w1, acc[0][1]);
            acc[0][2] = ffma2(xv.x, w2, acc[0][2]);
            acc[0][3] = ffma2(xv.x, w3, acc[0][3]);
            acc[1][0] = ffma2(xv.y, w0, acc[1][0]);
            acc[1][1] = ffma2(xv.y, w1, acc[1][1]);
            acc[1][2] = ffma2(xv.y, w2, acc[1][2]);
            acc[1][3] = ffma2(xv.y, w3, acc[1][3]);
        }
        __syncthreads();
    }
    float4 bb = *(const float4*)&bias[j0 + tj * 4];
    int co = j0 + tj * 4;
    #pragma unroll
    for (int r = 0; r < 4; r++) {
        int pr = r >> 1, hi = r & 1;
        float2 f0 = unpk(acc[pr][0]);
        float2 f1 = unpk(acc[pr][1]);
        float2 f2 = unpk(acc[pr][2]);
        float2 f3 = unpk(acc[pr][3]);
        float v0 = (hi ? f0.y : f0.x) + bb.x;
        float v1 = (hi ? f1.y : f1.x) + bb.y;
        float v2 = (hi ? f2.y : f2.x) + bb.z;
        float v3 = (hi ? f3.y : f3.x) + bb.w;
        __half* dst = outh + (size_t)(r0 + tb * 4 + r) * PP + co;
        *(__half2*)(dst)     = __floats2half2_rn(v0, v1);
        *(__half2*)(dst + 2) = __floats2half2_rn(v2, v3);
    }
}

// zero state rows, context0 = mean_s(values), reset flags
__global__ void init_kernel() {
    int gid = blockIdx.x * blockDim.x + threadIdx.x;   // 640*256 = 163840 threads
    if (gid < 1280 * BB) g_xT[128 * BB + gid] = 0.f;   // h1 slots + h2 slots
    if (gid < BB * PP) {
        int b = gid >> 7, p = gid & 127;
        float s = 0.f;
        for (int ss = 0; ss < SS; ss++) s += __half2float(g_valsh[((size_t)b * SS + ss) * PP + p]);
        g_xT[p * BB + b] = s * (1.f / SS);
    }
    if (gid < NCTA) g_flags[gid * 32] = 0u;
}

// ---------------- the persistent decode loop ----------------
// Two independent groups of 64 CTAs; group g owns batches [g*64, g*64+64).
__global__ __launch_bounds__(NTHR, 1) void loop_kernel(
    const int* __restrict__ y, const int* __restrict__ lens,
    const float* __restrict__ Wq, const float* __restrict__ bq,
    const float* __restrict__ emb, const float* __restrict__ bout,
    float* __restrict__ out) {
    __align__(16) __shared__ float sh[6592];
    const int cta = blockIdx.x;
    const int tid = threadIdx.x;
    const int g = cta >> 6;          // group
    const int c = cta & 63;          // index within group
    const int b0 = g * 64;           // batch base
    unsigned epoch = 0u;
    float c1r[2] = {0.f, 0.f};       // LSTM1 cell state (this thread's 2 cells)
    float c2r = 0.f;                 // LSTM2 cell state (threads < 128)

    for (int t = 0; t < TT; t++) {
        const int RA = 128 + (t & 1) * 512;          // h1 read slot
        const int WA = 128 + ((t & 1) ^ 1) * 512;    // h1 write slot
        const int RH = 1152 + (t & 1) * 128;         // h2 read slot
        const int WH = 1152 + ((t & 1) ^ 1) * 128;   // h2 write slot

        // ==== Stage A: LSTM1 GEMM (32 j x 64 b, K=640, no k-split) + fused cell ====
        {
            float* xs = sh;          // [64][68]
            float* ws = sh + 4352;   // [64][32]
            const int j0 = c * 32;   // global jn base (= 4 * hbase, hbase = c*8)
            const int tj = tid >> 4, tb = tid & 15;   // 2 j, 4 b per thread
            u64 acc[2][2];
            acc[0][0] = acc[0][1] = acc[1][0] = acc[1][1] = 0ull;
            float4 xpre[4];
            float2 wpre[4];
            // prologue prefetch chunk 0
            #pragma unroll
            for (int i = 0; i < 4; i++) {
                int kk = i * 16 + (tid >> 4);
                int k = kk;
                int row = (k < 128) ? k : (RA - 128 + k);
                xpre[i] = __ldcg((const float4*)&g_xT[row * BB + b0 + (tid & 15) * 4]);
            }
            #pragma unroll
            for (int i = 0; i < 4; i++) {
                int lin = i * 256 + tid;
                int kk = lin >> 4, j2 = lin & 15;
                __half2 hv = *(const __half2*)(g_W1h + (size_t)kk * G1 + j0 + j2 * 2);
                wpre[i] = __half22float2(hv);
            }
            for (int ch = 0; ch < 10; ch++) {
                #pragma unroll
                for (int i = 0; i < 4; i++) {
                    int kk = i * 16 + (tid >> 4);
                    *(float4*)&xs[kk * 68 + (tid & 15) * 4] = xpre[i];
                }
                #pragma unroll
                for (int i = 0; i < 4; i++) {
                    int lin = i * 256 + tid;
                    int kk = lin >> 4, j2 = lin & 15;
                    *(float2*)&ws[kk * 32 + j2 * 2] = wpre[i];
                }
                __syncthreads();
                if (ch < 9) {
                    #pragma unroll
                    for (int i = 0; i < 4; i++) {
                        int kk = i * 16 + (tid >> 4);
                        int k = (ch + 1) * 64 + kk;
                        int row = (k < 128) ? k : (RA - 128 + k);
                        xpre[i] = __ldcg((const float4*)&g_xT[row * BB + b0 + (tid & 15) * 4]);
                    }
                    #pragma unroll
                    for (int i = 0; i < 4; i++) {
                        int lin = i * 256 + tid;
                        int kk = lin >> 4, j2 = lin & 15;
                        __half2 hv = *(const __half2*)(g_W1h + (size_t)((ch + 1) * 64 + kk) * G1 + j0 + j2 * 2);
                        wpre[i] = __half22float2(hv);
                    }
                }
                #pragma unroll
                for (int kk = 0; kk < 64; kk++) {
                    float2 wv = *(const float2*)&ws[kk * 32 + tj * 2];
                    u64 w0 = pack2(wv.x), w1 = pack2(wv.y);
                    ulonglong2 xa = *(const ulonglong2*)&xs[kk * 68 + tb * 4];
                    acc[0][0] = ffma2(xa.x, w0, acc[0][0]);
                    acc[0][1] = ffma2(xa.y, w0, acc[0][1]);
                    acc[1][0] = ffma2(xa.x, w1, acc[1][0]);
                    acc[1][1] = ffma2(xa.y, w1, acc[1][1]);
                }
                __syncthreads();
            }
            // gates -> smem (alias xs region; xs dead)
            float* sgate = sh;       // [32][68]
            #pragma unroll
            for (int jj = 0; jj < 2; jj++)
                *(ulonglong2*)&sgate[(tj * 2 + jj) * 68 + tb * 4] =
                    make_ulonglong2(acc[jj][0], acc[jj][1]);
            int* stok = (int*)(sh + 6464);
            if (tid < 64) stok[tid] = (t == 0) ? 0 : y[(b0 + tid) * TT + t];
            __syncthreads();
            // fused LSTM1 cell: 8 h x 64 b, 2 per thread
            #pragma unroll
            for (int e = 0; e < 2; e++) {
                int idx = e * 256 + tid;
                int h = idx >> 6, b = idx & 63;
                int tok = stok[b];
                int jn = j0 + 4 * h;
                float gi = sgate[(4 * h + 0) * 68 + b] + g_MembT[(size_t)(jn + 0) * 32 + tok];
                float gf = sgate[(4 * h + 1) * 68 + b] + g_MembT[(size_t)(jn + 1) * 32 + tok];
                float gg = sgate[(4 * h + 2) * 68 + b] + g_MembT[(size_t)(jn + 2) * 32 + tok];
                float go = sgate[(4 * h + 3) * 68 + b] + g_MembT[(size_t)(jn + 3) * 32 + tok];
                float cc = sigf(gf) * c1r[e] + sigf(gi) * tanhf(gg);
                c1r[e] = cc;
                g_xT[(WA + c * 8 + h) * BB + b0 + b] = sigf(go) * tanhf(cc);
            }
        }
        groupbar(g, tid, epoch);

        // ==== Stage B2: LSTM2 GEMM (8 j x 64 b, K=640) + fused cell ====
        {
            float* xs  = sh;          // [64][68]
            float* ws2 = sh + 4352;   // [64][8]
            float* sg2 = sh + 4864;   // [8][66]
            const int j0B = c * 8;    // global jn base for LSTM2 (h2base = c*2)
            const int tj = tid >> 5, tb = tid & 31;   // 1 j, 2 b per thread
            u64 acc = 0ull;
            float4 xpre[4];
            float2 wpre;
            #pragma unroll
            for (int i = 0; i < 4; i++) {
                int kk = i * 16 + (tid >> 4);
                int kg = kk;
                int row = (kg < 512) ? (WA + kg) : (RH + kg - 512);
                xpre[i] = __ldcg((const float4*)&g_xT[row * BB + b0 + (tid & 15) * 4]);
            }
            {
                int kk = tid >> 2, j2 = tid & 3;
                __half2 hv = *(const __half2*)(g_W2h + (size_t)kk * G2 + j0B + j2 * 2);
                wpre = __half22float2(hv);
            }
            for (int ch = 0; ch < 10; ch++) {
                #pragma unroll
                for (int i = 0; i < 4; i++) {
                    int kk = i * 16 + (tid >> 4);
                    *(float4*)&xs[kk * 68 + (tid & 15) * 4] = xpre[i];
                }
                {
                    int kk = tid >> 2, j2 = tid & 3;
                    *(float2*)&ws2[kk * 8 + j2 * 2] = wpre;
                }
                __syncthreads();
                if (ch < 9) {
                    #pragma unroll
                    for (int i = 0; i < 4; i++) {
                        int kk = i * 16 + (tid >> 4);
                        int kg = (ch + 1) * 64 + kk;
                        int row = (kg < 512) ? (WA + kg) : (RH + kg - 512);
                        xpre[i] = __ldcg((const float4*)&g_xT[row * BB + b0 + (tid & 15) * 4]);
                    }
                    int kk = tid >> 2, j2 = tid & 3;
                    __half2 hv = *(const __half2*)(g_W2h + (size_t)((ch + 1) * 64 + kk) * G2 + j0B + j2 * 2);
                    wpre = __half22float2(hv);
                }
                #pragma unroll
                for (int kk = 0; kk < 64; kk++) {
                    u64 w0 = pack2(ws2[kk * 8 + tj]);
                    u64 xa = *(const u64*)&xs[kk * 68 + tb * 2];
                    acc = ffma2(xa, w0, acc);
                }
                __syncthreads();
            }
            *(u64*)&sg2[tj * 66 + tb * 2] = acc;
            __syncthreads();
            if (tid < 128) {
                int h = tid >> 6, b = tid & 63;
                int jn = j0B + 4 * h;
                float gi = sg2[(4 * h + 0) * 66 + b] + g_b2[jn + 0];
                float gf = sg2[(4 * h + 1) * 66 + b] + g_b2[jn + 1];
                float gg = sg2[(4 * h + 2) * 66 + b] + g_b2[jn + 2];
                float go = sg2[(4 * h + 3) * 66 + b] + g_b2[jn + 3];
                float cc = sigf(gf) * c2r + sigf(gi) * tanhf(gg);
                c2r = cc;
                g_xT[(WH + c * 2 + h) * BB + b0 + b] = sigf(go) * tanhf(cc);
            }
        }
        groupbar(g, tid, epoch);

        // ==== Stage C: per-batch CTA: q, attention, context, logits ====
        {
            const int b = b0 + c;
            float* h2s  = sh;            // 128
            float* qs   = sh + 128;      // 128 (reused as ctx)
            float* satt = sh + 256;      // 400
            float* red  = sh + 656;      // 8
            float* sinv = sh + 664;      // 1
            float* cred = sh + 672;      // 512

            if (tid < H2) h2s[tid] = __ldcg(&g_xT[(WH + tid) * BB + b]);
            __syncthreads();
            if (tid < PP) {
                const float4* wr = (const float4*)(Wq + tid * H2);
                const float4* h4 = (const float4*)h2s;
                float s = bq[tid];
                #pragma unroll 8
                for (int k4 = 0; k4 < 32; k4++) {
                    float4 w = wr[k4], h = h4[k4];
                    s += w.x*h.x + w.y*h.y + w.z*h.z + w.w*h.w;
                }
                qs[tid] = s;
            }
            __syncthreads();
            int lenb = lens[b];
            const float scale = 0.08838834764831845f;   // 1/sqrt(128)
            float pmax = -3.4e38f;
            for (int s = tid; s < SS; s += NTHR) {
                const uint4* kr = (const uint4*)(g_keysh + (size_t)(b * SS + s) * PP);
                const float4* q4 = (const float4*)qs;
                float d = 0.f;
                #pragma unroll
                for (int i = 0; i < 16; i++) {
                    uint4 u = kr[i];
                    const __half2* hp = (const __half2*)&u;
                    float2 f0 = __half22float2(hp[0]);
                    float2 f1 = __half22float2(hp[1]);
                    float2 f2 = __half22float2(hp[2]);
                    float2 f3 = __half22float2(hp[3]);
                    float4 qa = q4[2 * i], qb = q4[2 * i + 1];
                    d += f0.x*qa.x + f0.y*qa.y + f1.x*qa.z + f1.y*qa.w
                       + f2.x*qb.x + f2.y*qb.y + f3.x*qb.z + f3.y*qb.w;
                }
                d *= scale;
                if (s >= lenb) d = -1e9f;
                satt[s] = d;
                pmax = fmaxf(pmax, d);
            }
            float m = pmax;
            #pragma unroll
            for (int o = 16; o > 0; o >>= 1) m = fmaxf(m, __shfl_xor_sync(0xffffffffu, m, o));
            if ((tid & 31) == 0) red[tid >> 5] = m;
            __syncthreads();
            float mx = red[0];
            #pragma unroll
            for (int i = 1; i < 8; i++) mx = fmaxf(mx, red[i]);
            __syncthreads();
            float psum = 0.f;
            for (int s = tid; s < SS; s += NTHR) {
                float e = expf(satt[s] - mx);
                satt[s] = e;
                psum += e;
            }
            #pragma unroll
            for (int o = 16; o > 0; o >>= 1) psum += __shfl_xor_sync(0xffffffffu, psum, o);
            if ((tid & 31) == 0) red[tid >> 5] = psum;
            __syncthreads();
            if (tid == 0) {
                float s = 0.f;
                #pragma unroll
                for (int i = 0; i < 8; i++) s += red[i];
                sinv[0] = 1.f / s;
            }
            __syncthreads();
            float inv = sinv[0];
            {
                int p2 = tid & 63, sq = tid >> 6;    // 4 quarters of 100 s
                const __half2* vp = (const __half2*)g_valsh + ((size_t)b * SS + sq * 100) * 64 + p2;
                float cx0 = 0.f, cy0 = 0.f, cx1 = 0.f, cy1 = 0.f;
                #pragma unroll 4
                for (int s = 0; s < 100; s += 2) {
                    float2 v0 = __half22float2(vp[(size_t)s * 64]);
                    float2 v1 = __half22float2(vp[(size_t)(s + 1) * 64]);
                    float a0 = satt[sq * 100 + s];
                    float a1 = satt[sq * 100 + s + 1];
                    cx0 = fmaf(a0, v0.x, cx0); cy0 = fmaf(a0, v0.y, cy0);
                    cx1 = fmaf(a1, v1.x, cx1); cy1 = fmaf(a1, v1.y, cy1);
                }
                cred[sq * 128 + p2 * 2]     = cx0 + cx1;
                cred[sq * 128 + p2 * 2 + 1] = cy0 + cy1;
            }
            __syncthreads();
            if (tid < PP) {
                float cc = (cred[tid] + cred[128 + tid] + cred[256 + tid] + cred[384 + tid]) * inv;
                g_xT[tid * BB + b] = cc;   // ctx for next step
                qs[tid] = cc;
            }
            __syncthreads();
            // logits: 240 threads (30 v x 8 chunks of 32)
            {
                int v = tid >> 3, ch = tid & 7;
                float lg = 0.f;
                if (v < VV) {
                    const float* er = emb + v * EMBD + ch * 32;
                    const float* src = (ch < 4) ? (qs + ch * 32) : (h2s + (ch - 4) * 32);
                    #pragma unroll 8
                    for (int e = 0; e < 32; e++) lg += src[e] * er[e];
                }
                lg += __shfl_down_sync(0xffffffffu, lg, 4, 8);
                lg += __shfl_down_sync(0xffffffffu, lg, 2, 8);
                lg += __shfl_down_sync(0xffffffffu, lg, 1, 8);
                if (v < VV && ch == 0)
                    out[((size_t)b * VV + v) * TT + t] = lg + bout[v];   // predictions [B,V,T]
            }
            if (b == 0) {
                for (int s = tid; s < SS; s += NTHR)
                    out[PRED_N + t * SS + s] = satt[s] * inv;  // attention_plot [T,S]
            }
        }
        groupbar(g, tid, epoch);
    }
}

// ---------------- launch ----------------
extern "C" void kernel_launch(void* const* d_in, const int* in_sizes, int n_in,
                              void* d_out, int out_size) {
    (void)in_sizes; (void)n_in; (void)out_size;
    const float* enc  = (const float*)d_in[0];
    const int*   lens = (const int*)d_in[1];
    const int*   y    = (const int*)d_in[2];
    const float* emb  = (const float*)d_in[3];
    const float* Wih1 = (const float*)d_in[4];
    const float* Whh1 = (const float*)d_in[5];
    const float* bih1 = (const float*)d_in[6];
    const float* bhh1 = (const float*)d_in[7];
    const float* Wih2 = (const float*)d_in[8];
    const float* Whh2 = (const float*)d_in[9];
    const float* bih2 = (const float*)d_in[10];
    const float* bhh2 = (const float*)d_in[11];
    const float* Wk   = (const float*)d_in[12];
    const float* bk   = (const float*)d_in[13];
    const float* Wv   = (const float*)d_in[14];
    const float* bv   = (const float*)d_in[15];
    const float* Wq   = (const float*)d_in[16];
    const float* bq   = (const float*)d_in[17];
    const float* bout = (const float*)d_in[18];
    float* out = (float*)d_out;

    int prep_n = 640 * G1 + 640 * G2 + G2 + VV * G1;
    prep_kernel<<<(prep_n + 255) / 256, 256>>>(Wih1, Whh1, Wih2, Whh2,
                                               bih1, bhh1, bih2, bhh2, emb);
    kv_kernel<<<dim3(400, 8), 256>>>(enc, Wk, bk, Wv, bv);
    init_kernel<<<640, 256>>>();
    loop_kernel<<<NCTA, NTHR>>>(y, lens, Wq, bq, emb, bout, out);
}